// round 2
// baseline (speedup 1.0000x reference)
#include <cuda_runtime.h>
#include <math.h>

#define S_ 256
#define D_ 256
#define B_ 1024
#define LOG2PI 1.8378770664093453f

// Scratch (no runtime allocation allowed)
__device__ float g_M[S_ * D_ * D_];   // Gram matrices (lower triangle valid)
__device__ float g_W[S_ * D_ * D_];   // W = L^{-1}, full square (upper = 0)
__device__ float g_logdet[S_];

// ---------------------------------------------------------------------------
// Kernel 1: Gram. M[s] = Sp_s^T Sp_s. Only tiles (0,0),(1,0),(1,1) (lower).
// 128x128 tile per block, 256 threads, 8x8 micro-tile, K chunked by 16.
// ---------------------------------------------------------------------------
__global__ __launch_bounds__(256) void gram_kernel(const float* __restrict__ sp) {
    const int t = blockIdx.x;            // 0:(0,0) 1:(1,0) 2:(1,1)
    const int s = blockIdx.y;
    const int di = (t == 0) ? 0 : 1;
    const int ei = (t == 2) ? 1 : 0;
    const float* A = sp + s * D_ * D_;   // A[k*D + d]

    __shared__ float As[16][128];
    __shared__ float Bs[16][128];

    const int tid = threadIdx.x;
    const int tx = tid & 15, ty = tid >> 4;
    const int dBase = di * 128, eBase = ei * 128;

    float acc[8][8];
#pragma unroll
    for (int i = 0; i < 8; ++i)
#pragma unroll
        for (int j = 0; j < 8; ++j) acc[i][j] = 0.f;

    for (int k0 = 0; k0 < D_; k0 += 16) {
#pragma unroll
        for (int r = 0; r < 8; ++r) {
            int e = r * 256 + tid;
            int kk = e >> 7, dd = e & 127;
            As[kk][dd] = A[(k0 + kk) * D_ + dBase + dd];
            Bs[kk][dd] = A[(k0 + kk) * D_ + eBase + dd];
        }
        __syncthreads();
#pragma unroll
        for (int kk = 0; kk < 16; ++kk) {
            float4 a0 = *(const float4*)&As[kk][ty * 4];
            float4 a1 = *(const float4*)&As[kk][64 + ty * 4];
            float4 b0 = *(const float4*)&Bs[kk][tx * 4];
            float4 b1 = *(const float4*)&Bs[kk][64 + tx * 4];
            float av[8] = {a0.x, a0.y, a0.z, a0.w, a1.x, a1.y, a1.z, a1.w};
            float bv[8] = {b0.x, b0.y, b0.z, b0.w, b1.x, b1.y, b1.z, b1.w};
#pragma unroll
            for (int i = 0; i < 8; ++i)
#pragma unroll
                for (int j = 0; j < 8; ++j) acc[i][j] += av[i] * bv[j];
        }
        __syncthreads();
    }

    float* C = g_M + s * D_ * D_;
#pragma unroll
    for (int i = 0; i < 8; ++i) {
        int d = dBase + ((i < 4) ? (ty * 4 + i) : (64 + ty * 4 + (i - 4)));
        float4 v0 = make_float4(acc[i][0], acc[i][1], acc[i][2], acc[i][3]);
        float4 v1 = make_float4(acc[i][4], acc[i][5], acc[i][6], acc[i][7]);
        *(float4*)&C[d * D_ + eBase + tx * 4] = v0;
        *(float4*)&C[d * D_ + eBase + 64 + tx * 4] = v1;
    }
}

// ---------------------------------------------------------------------------
// Kernel 2: per-s ridge + Cholesky + logdet + triangular inversion (W=L^{-1}).
// One block per s, 256 threads, packed lower triangle in dynamic smem.
// ---------------------------------------------------------------------------
__global__ __launch_bounds__(256) void cholinv_kernel() {
    extern __shared__ float sh[];
    float* Lt  = sh;             // 32896 floats: packed lower triangle
    float* red = sh + 32896;     // 256 floats: reductions

    const int s = blockIdx.x;
    const int tid = threadIdx.x;
    const float* Ms = g_M + s * 65536;

    // Load lower triangle (coalesced along j)
    for (int i = 0; i < D_; ++i)
        for (int j = tid; j <= i; j += 256)
            Lt[i * (i + 1) / 2 + j] = Ms[i * D_ + j];
    __syncthreads();

    // Trace -> ridge -> add to diagonal
    float diagv = Lt[tid * (tid + 1) / 2 + tid];
    red[tid] = diagv;
    __syncthreads();
    for (int o = 128; o > 0; o >>= 1) {
        if (tid < o) red[tid] += red[tid + o];
        __syncthreads();
    }
    float ridge = 0.01f * red[0] / (float)D_;
    __syncthreads();                         // everyone has read red[0]
    Lt[tid * (tid + 1) / 2 + tid] = diagv + ridge;
    __syncthreads();

    // Left-looking Cholesky, one column at a time (thread tid -> row j+tid)
    for (int j = 0; j < D_; ++j) {
        int i = j + tid;
        float num = 0.f;
        if (i < D_) {
            const float* rowi = Lt + i * (i + 1) / 2;
            const float* rowj = Lt + j * (j + 1) / 2;
            num = rowi[j];
            for (int k = 0; k < j; ++k) num -= rowi[k] * rowj[k];
        }
        if (tid == 0) red[0] = num;
        __syncthreads();
        float dj = sqrtf(red[0]);
        if (i < D_) Lt[i * (i + 1) / 2 + j] = (tid == 0) ? dj : num / dj;
        __syncthreads();
    }

    // logdet = 2 * sum(log(diag(L)))
    red[tid] = 2.f * logf(Lt[tid * (tid + 1) / 2 + tid]);
    __syncthreads();
    for (int o = 128; o > 0; o >>= 1) {
        if (tid < o) red[tid] += red[tid + o];
        __syncthreads();
    }
    if (tid == 0) g_logdet[s] = red[0];

    // Inversion: thread tid owns column j=tid of W. Lockstep over i so the
    // global stores are coalesced; per-thread solve history in local array
    // indexed by (i - j) so LDL stays coalesced across lanes.
    const int j = tid;
    float w[256];
    float* Ws = g_W + s * 65536;
    for (int i = 0; i < D_; ++i) {
        float val = 0.f;
        if (i >= j) {
            const float* rowi = Lt + i * (i + 1) / 2;
            float acc2 = (i == j) ? 1.f : 0.f;
            int n = i - j;
            for (int it = 0; it < n; ++it) acc2 -= rowi[j + it] * w[it];
            val = acc2 / rowi[i];
            w[n] = val;
        }
        Ws[i * D_ + j] = val;    // coalesced across j; zeros fill the upper part
    }
}

// ---------------------------------------------------------------------------
// Kernel 3: maha GEMM + square-reduce epilogue.
// Block = (s, 128 b's). Loops d-tiles {0,1}; for d-tile 0, K stops at 128
// (W strictly lower-triangular beyond). out[b*S+s] = -0.5*(D log2pi + logdet + maha)
// ---------------------------------------------------------------------------
__global__ __launch_bounds__(256) void maha_kernel(const float* __restrict__ x,
                                                   const float* __restrict__ mu,
                                                   float* __restrict__ out) {
    __shared__ float Wt2[128 * 33];    // [row d][k] padded
    __shared__ float Xt2[128 * 33];    // [row b][k] padded
    __shared__ float mu_sm[D_];
    __shared__ float red[16 * 128];

    const int s = blockIdx.y;
    const int b0 = blockIdx.x * 128;
    const int tid = threadIdx.x;
    const int tx = tid & 15, ty = tid >> 4;
    const int lane = tid & 31, warp = tid >> 5;

    mu_sm[tid] = mu[s * D_ + tid];

    float bpart[8];
#pragma unroll
    for (int j = 0; j < 8; ++j) bpart[j] = 0.f;

    const float* Ws = g_W + s * 65536;

    for (int dt = 0; dt < 2; ++dt) {
        float acc[8][8];
#pragma unroll
        for (int i = 0; i < 8; ++i)
#pragma unroll
            for (int j = 0; j < 8; ++j) acc[i][j] = 0.f;

        const int d0 = dt * 128;
        const int kmax = (dt == 0) ? 128 : 256;

        for (int k0 = 0; k0 < kmax; k0 += 32) {
            __syncthreads();
#pragma unroll
            for (int r = 0; r < 16; ++r) {
                int dd = warp * 16 + r;
                Wt2[dd * 33 + lane] = Ws[(d0 + dd) * D_ + k0 + lane];
                Xt2[dd * 33 + lane] = x[(b0 + dd) * D_ + k0 + lane] - mu_sm[k0 + lane];
            }
            __syncthreads();
#pragma unroll 8
            for (int kk = 0; kk < 32; ++kk) {
                float av[8], bv[8];
#pragma unroll
                for (int i = 0; i < 4; ++i) {
                    av[i]     = Wt2[(ty * 4 + i) * 33 + kk];
                    av[4 + i] = Wt2[(64 + ty * 4 + i) * 33 + kk];
                }
#pragma unroll
                for (int j = 0; j < 4; ++j) {
                    bv[j]     = Xt2[(tx * 4 + j) * 33 + kk];
                    bv[4 + j] = Xt2[(64 + tx * 4 + j) * 33 + kk];
                }
#pragma unroll
                for (int i = 0; i < 8; ++i)
#pragma unroll
                    for (int j = 0; j < 8; ++j) acc[i][j] += av[i] * bv[j];
            }
        }
        // square + reduce this d-tile's contribution over the 8 d's
#pragma unroll
        for (int i = 0; i < 8; ++i)
#pragma unroll
            for (int j = 0; j < 8; ++j) bpart[j] += acc[i][j] * acc[i][j];
    }

    __syncthreads();
#pragma unroll
    for (int j = 0; j < 8; ++j) {
        int b = (j < 4) ? (tx * 4 + j) : (64 + tx * 4 + (j - 4));
        red[ty * 128 + b] = bpart[j];
    }
    __syncthreads();
    if (tid < 128) {
        float m = 0.f;
#pragma unroll
        for (int t2 = 0; t2 < 16; ++t2) m += red[t2 * 128 + tid];
        float lp = -0.5f * ((float)D_ * LOG2PI + g_logdet[s] + m);
        out[(b0 + tid) * S_ + s] = lp;
    }
}

// ---------------------------------------------------------------------------
extern "C" void kernel_launch(void* const* d_in, const int* in_sizes, int n_in,
                              void* d_out, int out_size) {
    const float* x  = (const float*)d_in[0];   // (B, D)
    const float* mu = (const float*)d_in[1];   // (S, 1, D)
    const float* sp = (const float*)d_in[2];   // (S, 1, D, D)
    float* out = (float*)d_out;                // (B, S)

    const int chol_smem = (32896 + 256) * sizeof(float);
    cudaFuncSetAttribute(cholinv_kernel,
                         cudaFuncAttributeMaxDynamicSharedMemorySize, chol_smem);

    gram_kernel<<<dim3(3, S_), 256>>>(sp);
    cholinv_kernel<<<S_, 256, chol_smem>>>();
    maha_kernel<<<dim3(B_ / 128, S_), 256>>>(x, mu, out);
}

// round 3
// speedup vs baseline: 1.3328x; 1.3328x over previous
#include <cuda_runtime.h>
#include <math.h>

#define S_ 256
#define D_ 256
#define B_ 1024
#define LOG2PI 1.8378770664093453f

// Scratch (no runtime allocation allowed)
__device__ float g_M[S_ * D_ * D_];   // Gram matrices (lower triangle valid)
__device__ float g_W[S_ * D_ * D_];   // W = L^{-1} (lower+diag valid; diag-block uppers zeroed)
__device__ float g_logdet[S_];

// Padded-packed lower-triangle row offset: row i starts at OFF(i), row length
// rounded up to 4 floats so every row base is 16B-aligned (float4-safe).
// OFF(i) = 4 * sum_{m=1..i} ceil(m/4) = 4*(q+1)*(2q+r), i = 4q+r.
__device__ __forceinline__ int OFF(int i) {
    int q = i >> 2, r = i & 3;
    return ((q + 1) * (2 * q + r)) << 2;
}
// Total floats: OFF(255) + 256 = 33024 + 256 = 33280

// ---------------------------------------------------------------------------
// Kernel 1: Gram. M[s] = Sp_s^T Sp_s. Only tiles (0,0),(1,0),(1,1) (lower).
// ---------------------------------------------------------------------------
__global__ __launch_bounds__(256) void gram_kernel(const float* __restrict__ sp) {
    const int t = blockIdx.x;            // 0:(0,0) 1:(1,0) 2:(1,1)
    const int s = blockIdx.y;
    const int di = (t == 0) ? 0 : 1;
    const int ei = (t == 2) ? 1 : 0;
    const float* A = sp + s * D_ * D_;   // A[k*D + d]

    __shared__ float As[16][128];
    __shared__ float Bs[16][128];

    const int tid = threadIdx.x;
    const int tx = tid & 15, ty = tid >> 4;
    const int dBase = di * 128, eBase = ei * 128;

    float acc[8][8];
#pragma unroll
    for (int i = 0; i < 8; ++i)
#pragma unroll
        for (int j = 0; j < 8; ++j) acc[i][j] = 0.f;

    for (int k0 = 0; k0 < D_; k0 += 16) {
#pragma unroll
        for (int r = 0; r < 8; ++r) {
            int e = r * 256 + tid;
            int kk = e >> 7, dd = e & 127;
            As[kk][dd] = A[(k0 + kk) * D_ + dBase + dd];
            Bs[kk][dd] = A[(k0 + kk) * D_ + eBase + dd];
        }
        __syncthreads();
#pragma unroll
        for (int kk = 0; kk < 16; ++kk) {
            float4 a0 = *(const float4*)&As[kk][ty * 4];
            float4 a1 = *(const float4*)&As[kk][64 + ty * 4];
            float4 b0 = *(const float4*)&Bs[kk][tx * 4];
            float4 b1 = *(const float4*)&Bs[kk][64 + tx * 4];
            float av[8] = {a0.x, a0.y, a0.z, a0.w, a1.x, a1.y, a1.z, a1.w};
            float bv[8] = {b0.x, b0.y, b0.z, b0.w, b1.x, b1.y, b1.z, b1.w};
#pragma unroll
            for (int i = 0; i < 8; ++i)
#pragma unroll
                for (int j = 0; j < 8; ++j) acc[i][j] += av[i] * bv[j];
        }
        __syncthreads();
    }

    float* C = g_M + s * D_ * D_;
#pragma unroll
    for (int i = 0; i < 8; ++i) {
        int d = dBase + ((i < 4) ? (ty * 4 + i) : (64 + ty * 4 + (i - 4)));
        float4 v0 = make_float4(acc[i][0], acc[i][1], acc[i][2], acc[i][3]);
        float4 v1 = make_float4(acc[i][4], acc[i][5], acc[i][6], acc[i][7]);
        *(float4*)&C[d * D_ + eBase + tx * 4] = v0;
        *(float4*)&C[d * D_ + eBase + 64 + tx * 4] = v1;
    }
}

// ---------------------------------------------------------------------------
// Kernel 2: ridge + Cholesky (float4 dots) + logdet + BLOCKED inversion.
// One block per s, 256 threads. No per-thread local arrays anywhere.
// smem: Lt (padded-packed L, 33280) | Wd (4 diag-inv blocks, 16384)
//       | Bb (64x64 staging, 4096) | red (256)  => ~216KB dynamic.
// ---------------------------------------------------------------------------
__global__ __launch_bounds__(256) void cholinv_kernel() {
    extern __shared__ float sh[];
    float* Lt  = sh;                 // 33280
    float* Wd  = sh + 33280;         // 16384: 4 x (64x64) inverted diag blocks
    float* Bb  = sh + 33280 + 16384; // 4096: 64x64 staging / T buffer
    float* red = sh + 33280 + 16384 + 4096; // 256

    const int s = blockIdx.x;
    const int tid = threadIdx.x;
    const float* Ms = g_M + s * 65536;
    float* Wg = g_W + s * 65536;

    // Load lower triangle (coalesced along j)
    for (int i = 0; i < D_; ++i) {
        int o = OFF(i);
        for (int j = tid; j <= i; j += 256) Lt[o + j] = Ms[i * D_ + j];
    }
    __syncthreads();

    // Trace -> ridge -> add to diagonal
    float diagv = Lt[OFF(tid) + tid];
    red[tid] = diagv;
    __syncthreads();
    for (int o = 128; o > 0; o >>= 1) {
        if (tid < o) red[tid] += red[tid + o];
        __syncthreads();
    }
    float ridge = 0.01f * red[0] / (float)D_;
    __syncthreads();
    Lt[OFF(tid) + tid] = diagv + ridge;
    __syncthreads();

    // Left-looking Cholesky, one column at a time (thread tid -> row j+tid).
    // Dot products vectorized float4 (rows are 16B-aligned).
    for (int j = 0; j < D_; ++j) {
        int i = j + tid;
        float num = 0.f;
        if (i < D_) {
            const float* ri = Lt + OFF(i);
            const float* rj = Lt + OFF(j);
            float a0 = 0.f, a1 = 0.f, a2 = 0.f, a3 = 0.f;
            int j4 = j & ~3;
            for (int k = 0; k < j4; k += 4) {
                float4 u = *(const float4*)(ri + k);
                float4 v = *(const float4*)(rj + k);
                a0 += u.x * v.x; a1 += u.y * v.y;
                a2 += u.z * v.z; a3 += u.w * v.w;
            }
            for (int k = j4; k < j; ++k) a0 += ri[k] * rj[k];
            num = ri[j] - ((a0 + a1) + (a2 + a3));
        }
        if (tid == 0) red[0] = num;
        __syncthreads();
        float dj = sqrtf(red[0]);
        if (i < D_) Lt[OFF(i) + j] = (tid == 0) ? dj : num / dj;
        __syncthreads();
    }

    // logdet = 2 * sum(log(diag(L)))
    red[tid] = 2.f * logf(Lt[OFF(tid) + tid]);
    __syncthreads();
    for (int o = 128; o > 0; o >>= 1) {
        if (tid < o) red[tid] += red[tid + o];
        __syncthreads();
    }
    if (tid == 0) g_logdet[s] = red[0];

    // ---- Blocked inversion: 64x64 blocks, W = L^{-1} ----
    // Zero the diag-inverse workspace (gives zero upper halves for free).
    for (int t = tid; t < 16384; t += 256) Wd[t] = 0.f;
    __syncthreads();

    // Phase A: invert 4 diagonal blocks in parallel; thread = (block K, col jj).
    // Solve history read straight back from smem (same thread wrote it).
    {
        const int K  = tid >> 6;
        const int jj = tid & 63;
        const int base = 64 * K;
        float* WK = Wd + K * 4096;
        for (int ii = 0; ii < 64; ++ii) {
            if (ii >= jj) {
                const float* ri = Lt + OFF(base + ii) + base;
                float acc = (ii == jj) ? 1.f : 0.f;
                for (int t = jj; t < ii; ++t) acc -= ri[t] * WK[t * 64 + jj];
                WK[ii * 64 + jj] = acc / ri[ii];
            }
        }
    }
    __syncthreads();

    // Copy diag blocks (incl. zero uppers) to global W
    for (int t = tid; t < 4 * 4096; t += 256) {
        int Kb = t >> 12, r = (t >> 6) & 63, c = t & 63;
        Wg[(64 * Kb + r) * D_ + 64 * Kb + c] = Wd[t];
    }
    __syncthreads();

    // Phase B: off-diagonal blocks. W(I,J) = -W(I,I) * sum_{K=J..I-1} L(I,K)*W(K,J)
    const int tr = tid & 15, tc = tid >> 4;
    const int r0 = tr * 4, c0 = tc * 4;
    for (int J = 0; J < 3; ++J) {
        for (int I = J + 1; I < 4; ++I) {
            float T[4][4];
#pragma unroll
            for (int r = 0; r < 4; ++r)
#pragma unroll
                for (int c = 0; c < 4; ++c) T[r][c] = 0.f;

            for (int K = J; K < I; ++K) {
                __syncthreads();   // protect Bb from prior readers
                // stage W(K,J) into Bb[k][c]
                for (int e = tid; e < 1024; e += 256) {
                    int k = e >> 4, c4 = (e & 15) * 4;
                    float4 v;
                    if (K == J) v = *(const float4*)&Wd[J * 4096 + k * 64 + c4];
                    else        v = *(const float4*)&Wg[(64 * K + k) * D_ + 64 * J + c4];
                    *(float4*)&Bb[k * 64 + c4] = v;
                }
                __syncthreads();
                const float* rA0 = Lt + OFF(64 * I + r0 + 0) + 64 * K;
                const float* rA1 = Lt + OFF(64 * I + r0 + 1) + 64 * K;
                const float* rA2 = Lt + OFF(64 * I + r0 + 2) + 64 * K;
                const float* rA3 = Lt + OFF(64 * I + r0 + 3) + 64 * K;
                for (int kk = 0; kk < 64; ++kk) {
                    float a0 = rA0[kk], a1 = rA1[kk], a2 = rA2[kk], a3 = rA3[kk];
                    float4 bv = *(const float4*)&Bb[kk * 64 + c0];
                    float bb[4] = {bv.x, bv.y, bv.z, bv.w};
#pragma unroll
                    for (int c = 0; c < 4; ++c) {
                        T[0][c] += a0 * bb[c];
                        T[1][c] += a1 * bb[c];
                        T[2][c] += a2 * bb[c];
                        T[3][c] += a3 * bb[c];
                    }
                }
            }
            // T -> Bb
            __syncthreads();
#pragma unroll
            for (int r = 0; r < 4; ++r) {
                float4 v = make_float4(T[r][0], T[r][1], T[r][2], T[r][3]);
                *(float4*)&Bb[(r0 + r) * 64 + c0] = v;
            }
            __syncthreads();
            // Wout = -Wd[I] @ T
            float O[4][4];
#pragma unroll
            for (int r = 0; r < 4; ++r)
#pragma unroll
                for (int c = 0; c < 4; ++c) O[r][c] = 0.f;
            const float* wA = Wd + I * 4096;
            for (int kk = 0; kk < 64; ++kk) {
                float a0 = wA[(r0 + 0) * 64 + kk];
                float a1 = wA[(r0 + 1) * 64 + kk];
                float a2 = wA[(r0 + 2) * 64 + kk];
                float a3 = wA[(r0 + 3) * 64 + kk];
                float4 bv = *(const float4*)&Bb[kk * 64 + c0];
                float bb[4] = {bv.x, bv.y, bv.z, bv.w};
#pragma unroll
                for (int c = 0; c < 4; ++c) {
                    O[0][c] += a0 * bb[c];
                    O[1][c] += a1 * bb[c];
                    O[2][c] += a2 * bb[c];
                    O[3][c] += a3 * bb[c];
                }
            }
#pragma unroll
            for (int r = 0; r < 4; ++r) {
                float4 v = make_float4(-O[r][0], -O[r][1], -O[r][2], -O[r][3]);
                *(float4*)&Wg[(64 * I + r0 + r) * D_ + 64 * J + c0] = v;
            }
        }
    }
}

// ---------------------------------------------------------------------------
// Kernel 3: maha GEMM + square-reduce epilogue.
// d-tiles of 64 (triangular factor 0.625), b-tile 128, 256 threads, 4x8 micro.
// ---------------------------------------------------------------------------
__global__ __launch_bounds__(256) void maha_kernel(const float* __restrict__ x,
                                                   const float* __restrict__ mu,
                                                   float* __restrict__ out) {
    __shared__ float Wt[64 * 33];    // [dd][kk]
    __shared__ float Xt[128 * 33];   // [bb][kk]
    __shared__ float mu_s[D_];
    __shared__ float red[16 * 128];

    const int s = blockIdx.y;
    const int b0 = blockIdx.x * 128;
    const int tid = threadIdx.x;
    const int tb = tid & 15, td = tid >> 4;

    mu_s[tid] = mu[s * D_ + tid];
    __syncthreads();

    float bp[8];
#pragma unroll
    for (int q = 0; q < 8; ++q) bp[q] = 0.f;

    const float* Wg = g_W + s * 65536;
    const int c4 = (tid & 7) * 4;
    const int row8 = tid >> 3;   // 0..31

    for (int dt = 0; dt < 4; ++dt) {
        float acc[4][8];
#pragma unroll
        for (int r = 0; r < 4; ++r)
#pragma unroll
            for (int c = 0; c < 8; ++c) acc[r][c] = 0.f;

        const int d0 = dt * 64;
        const int kmax = d0 + 64;

        for (int k0 = 0; k0 < kmax; k0 += 32) {
            __syncthreads();
            // stage W: Wt[dd][kk] <- Wg[(d0+dd)*256 + k0+kk]
#pragma unroll
            for (int h = 0; h < 2; ++h) {
                int dd = row8 + 32 * h;
                float4 v = *(const float4*)&Wg[(d0 + dd) * D_ + k0 + c4];
                Wt[dd * 33 + c4 + 0] = v.x;
                Wt[dd * 33 + c4 + 1] = v.y;
                Wt[dd * 33 + c4 + 2] = v.z;
                Wt[dd * 33 + c4 + 3] = v.w;
            }
            // stage X: Xt[bb][kk] <- x - mu
            float m0 = mu_s[k0 + c4 + 0], m1 = mu_s[k0 + c4 + 1];
            float m2 = mu_s[k0 + c4 + 2], m3 = mu_s[k0 + c4 + 3];
#pragma unroll
            for (int h = 0; h < 4; ++h) {
                int bb = row8 + 32 * h;
                float4 v = *(const float4*)&x[(b0 + bb) * D_ + k0 + c4];
                Xt[bb * 33 + c4 + 0] = v.x - m0;
                Xt[bb * 33 + c4 + 1] = v.y - m1;
                Xt[bb * 33 + c4 + 2] = v.z - m2;
                Xt[bb * 33 + c4 + 3] = v.w - m3;
            }
            __syncthreads();
#pragma unroll 4
            for (int kk = 0; kk < 32; ++kk) {
                float a[4], bv[8];
#pragma unroll
                for (int r = 0; r < 4; ++r) a[r] = Wt[(td * 4 + r) * 33 + kk];
#pragma unroll
                for (int q = 0; q < 4; ++q) {
                    bv[q]     = Xt[(tb * 4 + q) * 33 + kk];
                    bv[4 + q] = Xt[(64 + tb * 4 + q) * 33 + kk];
                }
#pragma unroll
                for (int r = 0; r < 4; ++r)
#pragma unroll
                    for (int c = 0; c < 8; ++c) acc[r][c] += a[r] * bv[c];
            }
        }
        // square + accumulate this d-tile's contribution
#pragma unroll
        for (int r = 0; r < 4; ++r)
#pragma unroll
            for (int c = 0; c < 8; ++c) bp[c] += acc[r][c] * acc[r][c];
    }

    __syncthreads();
#pragma unroll
    for (int q = 0; q < 8; ++q) {
        int b = (q < 4) ? (tb * 4 + q) : (64 + tb * 4 + (q - 4));
        red[td * 128 + b] = bp[q];
    }
    __syncthreads();
    if (tid < 128) {
        float m = 0.f;
#pragma unroll
        for (int t2 = 0; t2 < 16; ++t2) m += red[t2 * 128 + tid];
        out[(b0 + tid) * S_ + s] = -0.5f * ((float)D_ * LOG2PI + g_logdet[s] + m);
    }
}

// ---------------------------------------------------------------------------
extern "C" void kernel_launch(void* const* d_in, const int* in_sizes, int n_in,
                              void* d_out, int out_size) {
    const float* x  = (const float*)d_in[0];   // (B, D)
    const float* mu = (const float*)d_in[1];   // (S, 1, D)
    const float* sp = (const float*)d_in[2];   // (S, 1, D, D)
    float* out = (float*)d_out;                // (B, S)

    const int chol_smem = (33280 + 16384 + 4096 + 256) * sizeof(float);
    cudaFuncSetAttribute(cholinv_kernel,
                         cudaFuncAttributeMaxDynamicSharedMemorySize, chol_smem);

    gram_kernel<<<dim3(3, S_), 256>>>(sp);
    cholinv_kernel<<<S_, 256, chol_smem>>>();
    maha_kernel<<<dim3(B_ / 128, S_), 256>>>(x, mu, out);
}

// round 7
// speedup vs baseline: 2.1946x; 1.6466x over previous
#include <cuda_runtime.h>
#include <math.h>

#define S_ 256
#define D_ 256
#define B_ 1024
#define LOG2PI 1.8378770664093453f

// Scratch (no runtime allocation allowed)
__device__ float g_M[S_ * D_ * D_];    // Gram -> overwritten in place by L (lower)
__device__ float g_LT[S_ * D_ * D_];   // L transposed (k-major), lower part valid
__device__ float g_W[S_ * D_ * D_];    // W = L^{-1}
__device__ float g_logdet[S_];

// ---------------------------------------------------------------------------
// Kernel 1: Gram. M[s] = Sp_s^T Sp_s. Only tiles (0,0),(1,0),(1,1) (lower).
// ---------------------------------------------------------------------------
__global__ __launch_bounds__(256, 2) void gram_kernel(const float* __restrict__ sp) {
    const int t = blockIdx.x;            // 0:(0,0) 1:(1,0) 2:(1,1)
    const int s = blockIdx.y;
    const int di = (t == 0) ? 0 : 1;
    const int ei = (t == 2) ? 1 : 0;
    const float* A = sp + s * D_ * D_;   // A[k*D + d]

    __shared__ float As[16][128];
    __shared__ float Bs[16][128];

    const int tid = threadIdx.x;
    const int tx = tid & 15, ty = tid >> 4;
    const int dBase = di * 128, eBase = ei * 128;

    float acc[8][8];
#pragma unroll
    for (int i = 0; i < 8; ++i)
#pragma unroll
        for (int j = 0; j < 8; ++j) acc[i][j] = 0.f;

    for (int k0 = 0; k0 < D_; k0 += 16) {
#pragma unroll
        for (int r = 0; r < 8; ++r) {
            int e = r * 256 + tid;
            int kk = e >> 7, dd = e & 127;
            As[kk][dd] = A[(k0 + kk) * D_ + dBase + dd];
            Bs[kk][dd] = A[(k0 + kk) * D_ + eBase + dd];
        }
        __syncthreads();
#pragma unroll
        for (int kk = 0; kk < 16; ++kk) {
            float4 a0 = *(const float4*)&As[kk][ty * 4];
            float4 a1 = *(const float4*)&As[kk][64 + ty * 4];
            float4 b0 = *(const float4*)&Bs[kk][tx * 4];
            float4 b1 = *(const float4*)&Bs[kk][64 + tx * 4];
            float av[8] = {a0.x, a0.y, a0.z, a0.w, a1.x, a1.y, a1.z, a1.w};
            float bv[8] = {b0.x, b0.y, b0.z, b0.w, b1.x, b1.y, b1.z, b1.w};
#pragma unroll
            for (int i = 0; i < 8; ++i)
#pragma unroll
                for (int j = 0; j < 8; ++j) acc[i][j] += av[i] * bv[j];
        }
        __syncthreads();
    }

    float* C = g_M + s * D_ * D_;
#pragma unroll
    for (int i = 0; i < 8; ++i) {
        int d = dBase + ((i < 4) ? (ty * 4 + i) : (64 + ty * 4 + (i - 4)));
        float4 v0 = make_float4(acc[i][0], acc[i][1], acc[i][2], acc[i][3]);
        float4 v1 = make_float4(acc[i][4], acc[i][5], acc[i][6], acc[i][7]);
        *(float4*)&C[d * D_ + eBase + tx * 4] = v0;
        *(float4*)&C[d * D_ + eBase + 64 + tx * 4] = v1;
    }
}

// ---------------------------------------------------------------------------
// Kernel 2: blocked Cholesky (panel NB=64, GEMM history updates) + logdet +
// blocked inversion, fused. One block per s, 256 threads.
// smem: P[256][68] panel (reused as Wd[4][64*64] for inversion)
//       As[64][68], Bs[64][68] staging, red[256].  Total 105,472 B -> 2 blk/SM.
// ---------------------------------------------------------------------------
#define PPAD 68
#define P_FLOATS (256 * PPAD)            // 17408
#define STG_FLOATS (64 * PPAD)           // 4352
#define CHOL_SMEM_FLOATS (P_FLOATS + 2 * STG_FLOATS + 256)

__global__ __launch_bounds__(256) void cholinv_kernel() {
    extern __shared__ float sh[];
    float* P   = sh;                          // panel / Wd workspace
    float* As  = sh + P_FLOATS;               // staging A
    float* Bs  = sh + P_FLOATS + STG_FLOATS;  // staging B
    float* red = sh + P_FLOATS + 2 * STG_FLOATS;

    const int s = blockIdx.x;
    const int tid = threadIdx.x;
    const int sb = s * 65536;
    const float* Ms = g_M + sb;
    float* Mw = g_M + sb;
    float* LT = g_LT + sb;
    float* Wg = g_W + sb;

    const int rg = (tid >> 4) * 4;   // row group for GEMMs
    const int cg = (tid & 15) * 4;   // col group for GEMMs

    // ---- ridge from original diagonal ----
    red[tid] = Ms[tid * D_ + tid];
    __syncthreads();
    for (int o = 128; o > 0; o >>= 1) {
        if (tid < o) red[tid] += red[tid + o];
        __syncthreads();
    }
    const float ridge = 0.01f * red[0] / (float)D_;
    __syncthreads();

    // ---- blocked Cholesky ----
    for (int J = 0; J < 4; ++J) {
        const int R = 256 - 64 * J;      // panel rows
        const int g0 = 64 * J;           // global row/col base

        // load panel P[pr][c] = M[g0+pr][g0+c]
        for (int e = tid; e < R * 16; e += 256) {
            int pr = e >> 4, c4 = (e & 15) * 4;
            float4 v = *(const float4*)&Ms[(g0 + pr) * D_ + g0 + c4];
            *(float4*)&P[pr * PPAD + c4] = v;
        }
        __syncthreads();
        if (tid < 64) P[tid * PPAD + tid] += ridge;
        __syncthreads();

        // history update: P -= L(:,K) * L(J,K)^T  for K < J
        for (int K = 0; K < J; ++K) {
            __syncthreads();
            // Bs[k][c] = L[g0+c][64K+k]  (from LT, k-major)
            for (int e = tid; e < 1024; e += 256) {
                int k = e >> 4, c4 = (e & 15) * 4;
                float4 v = *(const float4*)&LT[(64 * K + k) * D_ + g0 + c4];
                *(float4*)&Bs[k * PPAD + c4] = v;
            }
            for (int I = J; I < 4; ++I) {
                __syncthreads();
                // As[k][r] = L[64I+r][64K+k]
                for (int e = tid; e < 1024; e += 256) {
                    int k = e >> 4, r4 = (e & 15) * 4;
                    float4 v = *(const float4*)&LT[(64 * K + k) * D_ + 64 * I + r4];
                    *(float4*)&As[k * PPAD + r4] = v;
                }
                __syncthreads();
                float acc[4][4];
#pragma unroll
                for (int r = 0; r < 4; ++r)
#pragma unroll
                    for (int c = 0; c < 4; ++c) acc[r][c] = 0.f;
#pragma unroll 4
                for (int kk = 0; kk < 64; ++kk) {
                    float4 a = *(const float4*)&As[kk * PPAD + rg];
                    float4 b = *(const float4*)&Bs[kk * PPAD + cg];
                    float av[4] = {a.x, a.y, a.z, a.w};
                    float bv[4] = {b.x, b.y, b.z, b.w};
#pragma unroll
                    for (int r = 0; r < 4; ++r)
#pragma unroll
                        for (int c = 0; c < 4; ++c) acc[r][c] += av[r] * bv[c];
                }
                const int prb = 64 * (I - J);
#pragma unroll
                for (int r = 0; r < 4; ++r)
#pragma unroll
                    for (int c = 0; c < 4; ++c)
                        P[(prb + rg + r) * PPAD + cg + c] -= acc[r][c];
            }
        }
        __syncthreads();

        // factor the 64-wide panel (left-looking within panel)
        for (int jj = 0; jj < 64; ++jj) {
            const int pr = jj + tid;
            const bool act = pr < R;
            float num = 0.f;
            if (act) {
                const float* rp = P + pr * PPAD;
                const float* rj = P + jj * PPAD;
                float a0 = 0.f, a1 = 0.f, a2 = 0.f, a3 = 0.f;
                const int j4 = jj & ~3;
                for (int k = 0; k < j4; k += 4) {
                    float4 u = *(const float4*)(rp + k);
                    float4 v = *(const float4*)(rj + k);
                    a0 += u.x * v.x; a1 += u.y * v.y;
                    a2 += u.z * v.z; a3 += u.w * v.w;
                }
                for (int k = j4; k < jj; ++k) a0 += rp[k] * rj[k];
                num = rp[jj] - ((a0 + a1) + (a2 + a3));
            }
            if (tid == 0) red[0] = num;
            __syncthreads();
            const float dj = sqrtf(red[0]);
            if (act) P[pr * PPAD + jj] = (tid == 0) ? dj : num / dj;
            __syncthreads();
        }

        // write panel back: g_M (row-major) and g_LT (k-major)
        for (int e = tid; e < R * 16; e += 256) {
            int pr = e >> 4, c4 = (e & 15) * 4;
            float4 v = *(const float4*)&P[pr * PPAD + c4];
            *(float4*)&Mw[(g0 + pr) * D_ + g0 + c4] = v;
        }
        for (int c = 0; c < 64; ++c) {
            for (int pr = tid; pr < R; pr += 256)
                LT[(g0 + c) * D_ + g0 + pr] = P[pr * PPAD + c];
        }
        __syncthreads();
    }

    // ---- logdet ----
    red[tid] = 2.f * logf(Mw[tid * D_ + tid]);
    __syncthreads();
    for (int o = 128; o > 0; o >>= 1) {
        if (tid < o) red[tid] += red[tid + o];
        __syncthreads();
    }
    if (tid == 0) g_logdet[s] = red[0];
    __syncthreads();

    // ================= blocked inversion: W = L^{-1} =================
    // Reuse P as Wd[4][64*64] (zero -> upper halves zero for free)
    for (int t = tid; t < 16384; t += 256) P[t] = 0.f;
    __syncthreads();

    // Phase A: invert diagonal blocks, 2 at a time (staged in As/Bs flat 64x64)
    for (int rnd = 0; rnd < 2; ++rnd) {
        for (int e = tid; e < 1024; e += 256) {
            int ii = e >> 4, t4 = (e & 15) * 4;
            int K0 = 2 * rnd, K1 = 2 * rnd + 1;
            *(float4*)&As[ii * 64 + t4] =
                *(const float4*)&Mw[(64 * K0 + ii) * D_ + 64 * K0 + t4];
            *(float4*)&Bs[ii * 64 + t4] =
                *(const float4*)&Mw[(64 * K1 + ii) * D_ + 64 * K1 + t4];
        }
        __syncthreads();
        if (tid < 128) {
            const int g = tid >> 6;
            const int jj = tid & 63;
            const int K = 2 * rnd + g;
            float* WK = P + K * 4096;
            const float* Ld = g ? Bs : As;
            for (int ii = jj; ii < 64; ++ii) {
                float acc = (ii == jj) ? 1.f : 0.f;
                for (int t = jj; t < ii; ++t) acc -= Ld[ii * 64 + t] * WK[t * 64 + jj];
                WK[ii * 64 + jj] = acc / Ld[ii * 64 + ii];
            }
        }
        __syncthreads();
    }

    // copy diag-inverse blocks (incl. zero uppers) to global W
    for (int e = tid; e < 16384; e += 256) {
        int Kb = e >> 12, rr = (e >> 6) & 63, cc = e & 63;
        Wg[(64 * Kb + rr) * D_ + 64 * Kb + cc] = P[e];
    }
    __syncthreads();

    // Phase B: W(I,J) = -Wd[I] * (sum_{K=J..I-1} L(I,K) * W(K,J))
    for (int J = 0; J < 3; ++J) {
        for (int I = J + 1; I < 4; ++I) {
            float acc[4][4];
#pragma unroll
            for (int r = 0; r < 4; ++r)
#pragma unroll
                for (int c = 0; c < 4; ++c) acc[r][c] = 0.f;

            for (int K = J; K < I; ++K) {
                __syncthreads();
                // As[k][r] = L[64I+r][64K+k] from LT
                for (int e = tid; e < 1024; e += 256) {
                    int k = e >> 4, r4 = (e & 15) * 4;
                    float4 v = *(const float4*)&LT[(64 * K + k) * D_ + 64 * I + r4];
                    *(float4*)&As[k * PPAD + r4] = v;
                }
                // Bs[k][c] = W[64K+k][64J+c]
                for (int e = tid; e < 1024; e += 256) {
                    int k = e >> 4, c4 = (e & 15) * 4;
                    float4 v;
                    if (K == J) {
                        v = make_float4(P[J * 4096 + k * 64 + c4 + 0],
                                        P[J * 4096 + k * 64 + c4 + 1],
                                        P[J * 4096 + k * 64 + c4 + 2],
                                        P[J * 4096 + k * 64 + c4 + 3]);
                    } else {
                        v = *(const float4*)&Wg[(64 * K + k) * D_ + 64 * J + c4];
                    }
                    *(float4*)&Bs[k * PPAD + c4] = v;
                }
                __syncthreads();
#pragma unroll 4
                for (int kk = 0; kk < 64; ++kk) {
                    float4 a = *(const float4*)&As[kk * PPAD + rg];
                    float4 b = *(const float4*)&Bs[kk * PPAD + cg];
                    float av[4] = {a.x, a.y, a.z, a.w};
                    float bv[4] = {b.x, b.y, b.z, b.w};
#pragma unroll
                    for (int r = 0; r < 4; ++r)
#pragma unroll
                        for (int c = 0; c < 4; ++c) acc[r][c] += av[r] * bv[c];
                }
            }
            // T -> Bs[k][c] layout (k = I-block row)
            __syncthreads();
#pragma unroll
            for (int r = 0; r < 4; ++r)
#pragma unroll
                for (int c = 0; c < 4; ++c)
                    Bs[(rg + r) * PPAD + cg + c] = acc[r][c];
            __syncthreads();
            // O = Wd[I] @ T
            float o[4][4];
#pragma unroll
            for (int r = 0; r < 4; ++r)
#pragma unroll
                for (int c = 0; c < 4; ++c) o[r][c] = 0.f;
            const float* wA = P + I * 4096;
#pragma unroll 4
            for (int kk = 0; kk < 64; ++kk) {
                float av[4];
#pragma unroll
                for (int r = 0; r < 4; ++r) av[r] = wA[(rg + r) * 64 + kk];
                float4 b = *(const float4*)&Bs[kk * PPAD + cg];
                float bv[4] = {b.x, b.y, b.z, b.w};
#pragma unroll
                for (int r = 0; r < 4; ++r)
#pragma unroll
                    for (int c = 0; c < 4; ++c) o[r][c] += av[r] * bv[c];
            }
#pragma unroll
            for (int r = 0; r < 4; ++r) {
                float4 v = make_float4(-o[r][0], -o[r][1], -o[r][2], -o[r][3]);
                *(float4*)&Wg[(64 * I + rg + r) * D_ + 64 * J + cg] = v;
            }
        }
    }
}

// ---------------------------------------------------------------------------
// Kernel 3: maha GEMM + square-reduce epilogue.
// ---------------------------------------------------------------------------
__global__ __launch_bounds__(256) void maha_kernel(const float* __restrict__ x,
                                                   const float* __restrict__ mu,
                                                   float* __restrict__ out) {
    __shared__ float Wt[64 * 33];
    __shared__ float Xt[128 * 33];
    __shared__ float mu_s[D_];
    __shared__ float red[16 * 128];

    const int s = blockIdx.y;
    const int b0 = blockIdx.x * 128;
    const int tid = threadIdx.x;
    const int tb = tid & 15, td = tid >> 4;

    mu_s[tid] = mu[s * D_ + tid];
    __syncthreads();

    float bp[8];
#pragma unroll
    for (int q = 0; q < 8; ++q) bp[q] = 0.f;

    const float* Wg = g_W + s * 65536;
    const int c4 = (tid & 7) * 4;
    const int row8 = tid >> 3;

    for (int dt = 0; dt < 4; ++dt) {
        float acc[4][8];
#pragma unroll
        for (int r = 0; r < 4; ++r)
#pragma unroll
            for (int c = 0; c < 8; ++c) acc[r][c] = 0.f;

        const int d0 = dt * 64;
        const int kmax = d0 + 64;

        for (int k0 = 0; k0 < kmax; k0 += 32) {
            __syncthreads();
#pragma unroll
            for (int h = 0; h < 2; ++h) {
                int dd = row8 + 32 * h;
                float4 v = *(const float4*)&Wg[(d0 + dd) * D_ + k0 + c4];
                Wt[dd * 33 + c4 + 0] = v.x;
                Wt[dd * 33 + c4 + 1] = v.y;
                Wt[dd * 33 + c4 + 2] = v.z;
                Wt[dd * 33 + c4 + 3] = v.w;
            }
            float m0 = mu_s[k0 + c4 + 0], m1 = mu_s[k0 + c4 + 1];
            float m2 = mu_s[k0 + c4 + 2], m3 = mu_s[k0 + c4 + 3];
#pragma unroll
            for (int h = 0; h < 4; ++h) {
                int bb = row8 + 32 * h;
                float4 v = *(const float4*)&x[(b0 + bb) * D_ + k0 + c4];
                Xt[bb * 33 + c4 + 0] = v.x - m0;
                Xt[bb * 33 + c4 + 1] = v.y - m1;
                Xt[bb * 33 + c4 + 2] = v.z - m2;
                Xt[bb * 33 + c4 + 3] = v.w - m3;
            }
            __syncthreads();
#pragma unroll 4
            for (int kk = 0; kk < 32; ++kk) {
                float a[4], bv[8];
#pragma unroll
                for (int r = 0; r < 4; ++r) a[r] = Wt[(td * 4 + r) * 33 + kk];
#pragma unroll
                for (int q = 0; q < 4; ++q) {
                    bv[q]     = Xt[(tb * 4 + q) * 33 + kk];
                    bv[4 + q] = Xt[(64 + tb * 4 + q) * 33 + kk];
                }
#pragma unroll
                for (int r = 0; r < 4; ++r)
#pragma unroll
                    for (int c = 0; c < 8; ++c) acc[r][c] += a[r] * bv[c];
            }
        }
#pragma unroll
        for (int r = 0; r < 4; ++r)
#pragma unroll
            for (int c = 0; c < 8; ++c) bp[c] += acc[r][c] * acc[r][c];
    }

    __syncthreads();
#pragma unroll
    for (int q = 0; q < 8; ++q) {
        int b = (q < 4) ? (tb * 4 + q) : (64 + tb * 4 + (q - 4));
        red[td * 128 + b] = bp[q];
    }
    __syncthreads();
    if (tid < 128) {
        float m = 0.f;
#pragma unroll
        for (int t2 = 0; t2 < 16; ++t2) m += red[t2 * 128 + tid];
        out[(b0 + tid) * S_ + s] = -0.5f * ((float)D_ * LOG2PI + g_logdet[s] + m);
    }
}

// ---------------------------------------------------------------------------
extern "C" void kernel_launch(void* const* d_in, const int* in_sizes, int n_in,
                              void* d_out, int out_size) {
    const float* x  = (const float*)d_in[0];   // (B, D)
    const float* mu = (const float*)d_in[1];   // (S, 1, D)
    const float* sp = (const float*)d_in[2];   // (S, 1, D, D)
    float* out = (float*)d_out;                // (B, S)

    const int chol_smem = CHOL_SMEM_FLOATS * sizeof(float);   // 105,472 B
    cudaFuncSetAttribute(cholinv_kernel,
                         cudaFuncAttributeMaxDynamicSharedMemorySize, chol_smem);

    gram_kernel<<<dim3(3, S_), 256>>>(sp);
    cholinv_kernel<<<S_, 256, chol_smem>>>();
    maha_kernel<<<dim3(B_ / 128, S_), 256>>>(x, mu, out);
}

// round 10
// speedup vs baseline: 3.0055x; 1.3695x over previous
#include <cuda_runtime.h>
#include <cuda_bf16.h>
#include <math.h>
#include <stdint.h>

#define S_ 256
#define D_ 256
#define B_ 1024
#define LOG2PI 1.8378770664093453f

// Scratch (no runtime allocation allowed)
__device__ float g_M[S_ * D_ * D_];    // Gram -> overwritten in place by L (lower)
__device__ float g_LT[S_ * D_ * D_];   // L transposed (k-major), lower part valid
__device__ float g_W[S_ * D_ * D_];    // W = L^{-1}, full 256x256 (uppers zeroed)
__device__ float g_logdet[S_];

// ---------------------------------------------------------------------------
// Kernel 1: Gram. M[s] = Sp_s^T Sp_s. Only tiles (0,0),(1,0),(1,1) (lower).
// ---------------------------------------------------------------------------
__global__ __launch_bounds__(256, 2) void gram_kernel(const float* __restrict__ sp) {
    const int t = blockIdx.x;            // 0:(0,0) 1:(1,0) 2:(1,1)
    const int s = blockIdx.y;
    const int di = (t == 0) ? 0 : 1;
    const int ei = (t == 2) ? 1 : 0;
    const float* A = sp + s * D_ * D_;   // A[k*D + d]

    __shared__ float As[16][128];
    __shared__ float Bs[16][128];

    const int tid = threadIdx.x;
    const int tx = tid & 15, ty = tid >> 4;
    const int dBase = di * 128, eBase = ei * 128;

    float acc[8][8];
#pragma unroll
    for (int i = 0; i < 8; ++i)
#pragma unroll
        for (int j = 0; j < 8; ++j) acc[i][j] = 0.f;

    for (int k0 = 0; k0 < D_; k0 += 16) {
#pragma unroll
        for (int r = 0; r < 8; ++r) {
            int e = r * 256 + tid;
            int kk = e >> 7, dd = e & 127;
            As[kk][dd] = A[(k0 + kk) * D_ + dBase + dd];
            Bs[kk][dd] = A[(k0 + kk) * D_ + eBase + dd];
        }
        __syncthreads();
#pragma unroll
        for (int kk = 0; kk < 16; ++kk) {
            float4 a0 = *(const float4*)&As[kk][ty * 4];
            float4 a1 = *(const float4*)&As[kk][64 + ty * 4];
            float4 b0 = *(const float4*)&Bs[kk][tx * 4];
            float4 b1 = *(const float4*)&Bs[kk][64 + tx * 4];
            float av[8] = {a0.x, a0.y, a0.z, a0.w, a1.x, a1.y, a1.z, a1.w};
            float bv[8] = {b0.x, b0.y, b0.z, b0.w, b1.x, b1.y, b1.z, b1.w};
#pragma unroll
            for (int i = 0; i < 8; ++i)
#pragma unroll
                for (int j = 0; j < 8; ++j) acc[i][j] += av[i] * bv[j];
        }
        __syncthreads();
    }

    float* C = g_M + s * D_ * D_;
#pragma unroll
    for (int i = 0; i < 8; ++i) {
        int d = dBase + ((i < 4) ? (ty * 4 + i) : (64 + ty * 4 + (i - 4)));
        float4 v0 = make_float4(acc[i][0], acc[i][1], acc[i][2], acc[i][3]);
        float4 v1 = make_float4(acc[i][4], acc[i][5], acc[i][6], acc[i][7]);
        *(float4*)&C[d * D_ + eBase + tx * 4] = v0;
        *(float4*)&C[d * D_ + eBase + 64 + tx * 4] = v1;
    }
}

// ---------------------------------------------------------------------------
// Kernel 2: blocked Cholesky + logdet + blocked inversion + upper-zeroing of W.
// ---------------------------------------------------------------------------
#define PPAD 68
#define P_FLOATS (256 * PPAD)
#define STG_FLOATS (64 * PPAD)
#define CHOL_SMEM_FLOATS (P_FLOATS + 2 * STG_FLOATS + 256)

__global__ __launch_bounds__(256) void cholinv_kernel() {
    extern __shared__ float sh[];
    float* P   = sh;
    float* As  = sh + P_FLOATS;
    float* Bs  = sh + P_FLOATS + STG_FLOATS;
    float* red = sh + P_FLOATS + 2 * STG_FLOATS;

    const int s = blockIdx.x;
    const int tid = threadIdx.x;
    const int sb = s * 65536;
    const float* Ms = g_M + sb;
    float* Mw = g_M + sb;
    float* LT = g_LT + sb;
    float* Wg = g_W + sb;

    const int rg = (tid >> 4) * 4;
    const int cg = (tid & 15) * 4;

    red[tid] = Ms[tid * D_ + tid];
    __syncthreads();
    for (int o = 128; o > 0; o >>= 1) {
        if (tid < o) red[tid] += red[tid + o];
        __syncthreads();
    }
    const float ridge = 0.01f * red[0] / (float)D_;
    __syncthreads();

    for (int J = 0; J < 4; ++J) {
        const int R = 256 - 64 * J;
        const int g0 = 64 * J;

        for (int e = tid; e < R * 16; e += 256) {
            int pr = e >> 4, c4 = (e & 15) * 4;
            float4 v = *(const float4*)&Ms[(g0 + pr) * D_ + g0 + c4];
            *(float4*)&P[pr * PPAD + c4] = v;
        }
        __syncthreads();
        if (tid < 64) P[tid * PPAD + tid] += ridge;
        __syncthreads();

        for (int K = 0; K < J; ++K) {
            __syncthreads();
            for (int e = tid; e < 1024; e += 256) {
                int k = e >> 4, c4 = (e & 15) * 4;
                float4 v = *(const float4*)&LT[(64 * K + k) * D_ + g0 + c4];
                *(float4*)&Bs[k * PPAD + c4] = v;
            }
            for (int I = J; I < 4; ++I) {
                __syncthreads();
                for (int e = tid; e < 1024; e += 256) {
                    int k = e >> 4, r4 = (e & 15) * 4;
                    float4 v = *(const float4*)&LT[(64 * K + k) * D_ + 64 * I + r4];
                    *(float4*)&As[k * PPAD + r4] = v;
                }
                __syncthreads();
                float acc[4][4];
#pragma unroll
                for (int r = 0; r < 4; ++r)
#pragma unroll
                    for (int c = 0; c < 4; ++c) acc[r][c] = 0.f;
#pragma unroll 4
                for (int kk = 0; kk < 64; ++kk) {
                    float4 a = *(const float4*)&As[kk * PPAD + rg];
                    float4 b = *(const float4*)&Bs[kk * PPAD + cg];
                    float av[4] = {a.x, a.y, a.z, a.w};
                    float bv[4] = {b.x, b.y, b.z, b.w};
#pragma unroll
                    for (int r = 0; r < 4; ++r)
#pragma unroll
                        for (int c = 0; c < 4; ++c) acc[r][c] += av[r] * bv[c];
                }
                const int prb = 64 * (I - J);
#pragma unroll
                for (int r = 0; r < 4; ++r)
#pragma unroll
                    for (int c = 0; c < 4; ++c)
                        P[(prb + rg + r) * PPAD + cg + c] -= acc[r][c];
            }
        }
        __syncthreads();

        for (int jj = 0; jj < 64; ++jj) {
            const int pr = jj + tid;
            const bool act = pr < R;
            float num = 0.f;
            if (act) {
                const float* rp = P + pr * PPAD;
                const float* rj = P + jj * PPAD;
                float a0 = 0.f, a1 = 0.f, a2 = 0.f, a3 = 0.f;
                const int j4 = jj & ~3;
                for (int k = 0; k < j4; k += 4) {
                    float4 u = *(const float4*)(rp + k);
                    float4 v = *(const float4*)(rj + k);
                    a0 += u.x * v.x; a1 += u.y * v.y;
                    a2 += u.z * v.z; a3 += u.w * v.w;
                }
                for (int k = j4; k < jj; ++k) a0 += rp[k] * rj[k];
                num = rp[jj] - ((a0 + a1) + (a2 + a3));
            }
            if (tid == 0) red[0] = num;
            __syncthreads();
            const float dj = sqrtf(red[0]);
            if (act) P[pr * PPAD + jj] = (tid == 0) ? dj : num / dj;
            __syncthreads();
        }

        for (int e = tid; e < R * 16; e += 256) {
            int pr = e >> 4, c4 = (e & 15) * 4;
            float4 v = *(const float4*)&P[pr * PPAD + c4];
            *(float4*)&Mw[(g0 + pr) * D_ + g0 + c4] = v;
        }
        for (int c = 0; c < 64; ++c) {
            for (int pr = tid; pr < R; pr += 256)
                LT[(g0 + c) * D_ + g0 + pr] = P[pr * PPAD + c];
        }
        __syncthreads();
    }

    red[tid] = 2.f * logf(Mw[tid * D_ + tid]);
    __syncthreads();
    for (int o = 128; o > 0; o >>= 1) {
        if (tid < o) red[tid] += red[tid + o];
        __syncthreads();
    }
    if (tid == 0) g_logdet[s] = red[0];
    __syncthreads();

    // ===== blocked inversion: W = L^{-1} =====
    for (int t = tid; t < 16384; t += 256) P[t] = 0.f;
    __syncthreads();

    for (int rnd = 0; rnd < 2; ++rnd) {
        for (int e = tid; e < 1024; e += 256) {
            int ii = e >> 4, t4 = (e & 15) * 4;
            int K0 = 2 * rnd, K1 = 2 * rnd + 1;
            *(float4*)&As[ii * 64 + t4] =
                *(const float4*)&Mw[(64 * K0 + ii) * D_ + 64 * K0 + t4];
            *(float4*)&Bs[ii * 64 + t4] =
                *(const float4*)&Mw[(64 * K1 + ii) * D_ + 64 * K1 + t4];
        }
        __syncthreads();
        if (tid < 128) {
            const int g = tid >> 6;
            const int jj = tid & 63;
            const int K = 2 * rnd + g;
            float* WK = P + K * 4096;
            const float* Ld = g ? Bs : As;
            for (int ii = jj; ii < 64; ++ii) {
                float acc = (ii == jj) ? 1.f : 0.f;
                for (int t = jj; t < ii; ++t) acc -= Ld[ii * 64 + t] * WK[t * 64 + jj];
                WK[ii * 64 + jj] = acc / Ld[ii * 64 + ii];
            }
        }
        __syncthreads();
    }

    // copy diag-inverse blocks (incl. zero uppers) to global W
    for (int e = tid; e < 16384; e += 256) {
        int Kb = e >> 12, rr = (e >> 6) & 63, cc = e & 63;
        Wg[(64 * Kb + rr) * D_ + 64 * Kb + cc] = P[e];
    }
    // zero the 6 strictly-upper 64x64 blocks (tensor-core maha sweeps them)
    for (int e = tid; e < 6 * 4096; e += 256) {
        int bb = e >> 12, rr = (e >> 6) & 63, cc = e & 63;
        int I = (bb < 3) ? 0 : ((bb < 5) ? 1 : 2);
        int J = (bb < 3) ? (bb + 1) : ((bb == 3) ? 2 : 3);
        Wg[(64 * I + rr) * D_ + 64 * J + cc] = 0.f;
    }
    __syncthreads();

    // Phase B: W(I,J) = -Wd[I] * (sum_{K=J..I-1} L(I,K) * W(K,J))
    for (int J = 0; J < 3; ++J) {
        for (int I = J + 1; I < 4; ++I) {
            float acc[4][4];
#pragma unroll
            for (int r = 0; r < 4; ++r)
#pragma unroll
                for (int c = 0; c < 4; ++c) acc[r][c] = 0.f;

            for (int K = J; K < I; ++K) {
                __syncthreads();
                for (int e = tid; e < 1024; e += 256) {
                    int k = e >> 4, r4 = (e & 15) * 4;
                    float4 v = *(const float4*)&LT[(64 * K + k) * D_ + 64 * I + r4];
                    *(float4*)&As[k * PPAD + r4] = v;
                }
                for (int e = tid; e < 1024; e += 256) {
                    int k = e >> 4, c4 = (e & 15) * 4;
                    float4 v;
                    if (K == J) {
                        v = make_float4(P[J * 4096 + k * 64 + c4 + 0],
                                        P[J * 4096 + k * 64 + c4 + 1],
                                        P[J * 4096 + k * 64 + c4 + 2],
                                        P[J * 4096 + k * 64 + c4 + 3]);
                    } else {
                        v = *(const float4*)&Wg[(64 * K + k) * D_ + 64 * J + c4];
                    }
                    *(float4*)&Bs[k * PPAD + c4] = v;
                }
                __syncthreads();
#pragma unroll 4
                for (int kk = 0; kk < 64; ++kk) {
                    float4 a = *(const float4*)&As[kk * PPAD + rg];
                    float4 b = *(const float4*)&Bs[kk * PPAD + cg];
                    float av[4] = {a.x, a.y, a.z, a.w};
                    float bv[4] = {b.x, b.y, b.z, b.w};
#pragma unroll
                    for (int r = 0; r < 4; ++r)
#pragma unroll
                        for (int c = 0; c < 4; ++c) acc[r][c] += av[r] * bv[c];
                }
            }
            __syncthreads();
#pragma unroll
            for (int r = 0; r < 4; ++r)
#pragma unroll
                for (int c = 0; c < 4; ++c)
                    Bs[(rg + r) * PPAD + cg + c] = acc[r][c];
            __syncthreads();
            float o[4][4];
#pragma unroll
            for (int r = 0; r < 4; ++r)
#pragma unroll
                for (int c = 0; c < 4; ++c) o[r][c] = 0.f;
            const float* wA = P + I * 4096;
#pragma unroll 4
            for (int kk = 0; kk < 64; ++kk) {
                float av[4];
#pragma unroll
                for (int r = 0; r < 4; ++r) av[r] = wA[(rg + r) * 64 + kk];
                float4 b = *(const float4*)&Bs[kk * PPAD + cg];
                float bv[4] = {b.x, b.y, b.z, b.w};
#pragma unroll
                for (int r = 0; r < 4; ++r)
#pragma unroll
                    for (int c = 0; c < 4; ++c) o[r][c] += av[r] * bv[c];
            }
#pragma unroll
            for (int r = 0; r < 4; ++r) {
                float4 v = make_float4(-o[r][0], -o[r][1], -o[r][2], -o[r][3]);
                *(float4*)&Wg[(64 * I + rg + r) * D_ + 64 * J + cg] = v;
            }
        }
    }
}

// ---------------------------------------------------------------------------
// mma.sync helpers (plain sm_80+ PTX; assembles at .target sm_103)
// ---------------------------------------------------------------------------
__device__ __forceinline__ uint32_t smem_u32(const void* p) {
    uint32_t a;
    asm("{ .reg .u64 t; cvta.to.shared.u64 t, %1; cvt.u32.u64 %0, t; }"
        : "=r"(a) : "l"(p));
    return a;
}
#define LDSM_X4(r, addr) \
    asm volatile("ldmatrix.sync.aligned.m8n8.x4.shared.b16 {%0,%1,%2,%3}, [%4];" \
                 : "=r"((r)[0]), "=r"((r)[1]), "=r"((r)[2]), "=r"((r)[3]) \
                 : "r"(addr))
#define LDSM_X2(r, addr) \
    asm volatile("ldmatrix.sync.aligned.m8n8.x2.shared.b16 {%0,%1}, [%2];" \
                 : "=r"((r)[0]), "=r"((r)[1]) : "r"(addr))
#define MMA16816(c, a, b) \
    asm volatile("mma.sync.aligned.m16n8k16.row.col.f32.bf16.bf16.f32 " \
                 "{%0,%1,%2,%3}, {%4,%5,%6,%7}, {%8,%9}, {%0,%1,%2,%3};" \
                 : "+f"((c)[0]), "+f"((c)[1]), "+f"((c)[2]), "+f"((c)[3]) \
                 : "r"((a)[0]), "r"((a)[1]), "r"((a)[2]), "r"((a)[3]), \
                   "r"((b)[0]), "r"((b)[1]))

__device__ __forceinline__ uint32_t pack_split(float f0, float f1, uint32_t& lo) {
    __nv_bfloat16 h0 = __float2bfloat16(f0);
    __nv_bfloat16 h1 = __float2bfloat16(f1);
    __nv_bfloat16 l0 = __float2bfloat16(f0 - __bfloat162float(h0));
    __nv_bfloat16 l1 = __float2bfloat16(f1 - __bfloat162float(h1));
    __nv_bfloat162 hp = __halves2bfloat162(h0, h1);
    __nv_bfloat162 lp = __halves2bfloat162(l0, l1);
    lo = *(uint32_t*)&lp;
    return *(uint32_t*)&hp;
}
__device__ __forceinline__ void split8(float4 a, float4 b, uint4& h, uint4& l) {
    h.x = pack_split(a.x, a.y, l.x);
    h.y = pack_split(a.z, a.w, l.y);
    h.z = pack_split(b.x, b.y, l.z);
    h.w = pack_split(b.z, b.w, l.w);
}

// ---------------------------------------------------------------------------
// Kernel 3: maha via mma.sync bf16 split GEMM + square-reduce epilogue.
// Block = (s, 128 b's). 8 warps in 2x4 grid; warp tile 64(d) x 32(b).
// K staged in 64-chunks as bf16 hi/lo, row stride 72 elems (144B, odd 16B
// segments -> conflict-free ldmatrix). d-tile 0 stops at K=128 (W triangular).
// ---------------------------------------------------------------------------
#define ASTRIDE 72
#define ABUF (128 * ASTRIDE)             // bf16 elements per buffer
#define MAHA_SMEM (4 * ABUF * 2 + 256 * 4)

__global__ __launch_bounds__(256) void maha_mma_kernel(const float* __restrict__ x,
                                                       const float* __restrict__ mu,
                                                       float* __restrict__ out) {
    extern __shared__ char shm[];
    __nv_bfloat16* AH = (__nv_bfloat16*)shm;
    __nv_bfloat16* AL = AH + ABUF;
    __nv_bfloat16* BH = AL + ABUF;
    __nv_bfloat16* BL = BH + ABUF;
    float* sacc = (float*)(shm + 4 * ABUF * 2);   // [2 warp-rows][128 cols]

    const int s = blockIdx.y;
    const int b0 = blockIdx.x * 128;
    const int tid = threadIdx.x;
    const int wid = tid >> 5, lane = tid & 31;
    const int wr = wid >> 2;        // 0..1 : d-offset wr*64 within d-tile
    const int wc = wid & 3;         // 0..3 : b-offset wc*32

    sacc[tid] = 0.f;
    __syncthreads();

    const float* Wbase = g_W + s * 65536;
    const int srow = tid >> 3;              // 0..31 (staging row group)
    const int sk8  = (tid & 7) * 8;         // staging k offset

    for (int dt = 0; dt < 2; ++dt) {
        float c[4][4][4];
#pragma unroll
        for (int mt = 0; mt < 4; ++mt)
#pragma unroll
            for (int nt = 0; nt < 4; ++nt)
#pragma unroll
                for (int q = 0; q < 4; ++q) c[mt][nt][q] = 0.f;

        const int nch = dt ? 4 : 2;          // d-tile 0: W zero beyond k=128
        for (int ch = 0; ch < nch; ++ch) {
            const int k0 = ch * 64;
            __syncthreads();                 // prior chunk's ldmatrix done
            // ---- stage A = W[dt*128 + row][k0 + k] as bf16 hi/lo ----
            const float* Wr = Wbase + (dt * 128) * 256 + k0;
#pragma unroll
            for (int it = 0; it < 4; ++it) {
                int row = srow + it * 32;
                const float* p = Wr + row * 256 + sk8;
                float4 u = *(const float4*)p;
                float4 v = *(const float4*)(p + 4);
                uint4 hq, lq; split8(u, v, hq, lq);
                *(uint4*)(AH + row * ASTRIDE + sk8) = hq;
                *(uint4*)(AL + row * ASTRIDE + sk8) = lq;
            }
            // ---- stage B = x[b0+row] - mu[s] ----
#pragma unroll
            for (int it = 0; it < 4; ++it) {
                int row = srow + it * 32;
                const float* px = x + (b0 + row) * 256 + k0 + sk8;
                const float* pm = mu + s * 256 + k0 + sk8;
                float4 u = *(const float4*)px;
                float4 um = *(const float4*)pm;
                float4 v = *(const float4*)(px + 4);
                float4 vm = *(const float4*)(pm + 4);
                u.x -= um.x; u.y -= um.y; u.z -= um.z; u.w -= um.w;
                v.x -= vm.x; v.y -= vm.y; v.z -= vm.z; v.w -= vm.w;
                uint4 hq, lq; split8(u, v, hq, lq);
                *(uint4*)(BH + row * ASTRIDE + sk8) = hq;
                *(uint4*)(BL + row * ASTRIDE + sk8) = lq;
            }
            __syncthreads();

            // ---- compute: 4 k16 steps, 3 passes (HH, HL, LH) ----
            const int ar = lane & 15, as8 = (lane >> 4) * 8;
            const int br = lane & 7,  bs8 = ((lane >> 3) & 1) * 8;
#pragma unroll
            for (int ks = 0; ks < 4; ++ks) {
                const int kk = ks * 16;
                uint32_t aH[4][4], aL[4][4], bH[4][2], bL[4][2];
#pragma unroll
                for (int mt = 0; mt < 4; ++mt) {
                    int row = wr * 64 + mt * 16 + ar;
                    uint32_t ah = smem_u32(AH + row * ASTRIDE + kk + as8);
                    uint32_t al = smem_u32(AL + row * ASTRIDE + kk + as8);
                    LDSM_X4(aH[mt], ah);
                    LDSM_X4(aL[mt], al);
                }
#pragma unroll
                for (int nt = 0; nt < 4; ++nt) {
                    int row = wc * 32 + nt * 8 + br;
                    uint32_t bh = smem_u32(BH + row * ASTRIDE + kk + bs8);
                    uint32_t bl = smem_u32(BL + row * ASTRIDE + kk + bs8);
                    LDSM_X2(bH[nt], bh);
                    LDSM_X2(bL[nt], bl);
                }
#pragma unroll
                for (int mt = 0; mt < 4; ++mt)
#pragma unroll
                    for (int nt = 0; nt < 4; ++nt) {
                        MMA16816(c[mt][nt], aH[mt], bH[nt]);
                        MMA16816(c[mt][nt], aH[mt], bL[nt]);
                        MMA16816(c[mt][nt], aL[mt], bH[nt]);
                    }
            }
        }

        // ---- epilogue: square + reduce over d within warp, slot-accumulate ----
#pragma unroll
        for (int nt = 0; nt < 4; ++nt) {
            float p0 = 0.f, p1 = 0.f;
#pragma unroll
            for (int mt = 0; mt < 4; ++mt) {
                p0 += c[mt][nt][0] * c[mt][nt][0] + c[mt][nt][2] * c[mt][nt][2];
                p1 += c[mt][nt][1] * c[mt][nt][1] + c[mt][nt][3] * c[mt][nt][3];
            }
            // sum the 8 lanes sharing lane%4 (rows of the m16 tiles)
#pragma unroll
            for (int m = 4; m <= 16; m <<= 1) {
                p0 += __shfl_xor_sync(0xffffffffu, p0, m);
                p1 += __shfl_xor_sync(0xffffffffu, p1, m);
            }
            if (lane < 4) {
                int col = wc * 32 + nt * 8 + 2 * lane;
                sacc[wr * 128 + col]     += p0;
                sacc[wr * 128 + col + 1] += p1;
            }
        }
    }

    __syncthreads();
    if (tid < 128) {
        float m = sacc[tid] + sacc[128 + tid];
        out[(b0 + tid) * S_ + s] = -0.5f * ((float)D_ * LOG2PI + g_logdet[s] + m);
    }
}

// ---------------------------------------------------------------------------
extern "C" void kernel_launch(void* const* d_in, const int* in_sizes, int n_in,
                              void* d_out, int out_size) {
    const float* x  = (const float*)d_in[0];   // (B, D)
    const float* mu = (const float*)d_in[1];   // (S, 1, D)
    const float* sp = (const float*)d_in[2];   // (S, 1, D, D)
    float* out = (float*)d_out;                // (B, S)

    const int chol_smem = CHOL_SMEM_FLOATS * sizeof(float);   // 105,472 B
    cudaFuncSetAttribute(cholinv_kernel,
                         cudaFuncAttributeMaxDynamicSharedMemorySize, chol_smem);
    cudaFuncSetAttribute(maha_mma_kernel,
                         cudaFuncAttributeMaxDynamicSharedMemorySize, MAHA_SMEM);

    gram_kernel<<<dim3(3, S_), 256>>>(sp);
    cholinv_kernel<<<S_, 256, chol_smem>>>();
    maha_mma_kernel<<<dim3(B_ / 128, S_), 256, MAHA_SMEM>>>(x, mu, out);
}

// round 14
// speedup vs baseline: 3.0470x; 1.0138x over previous
#include <cuda_runtime.h>
#include <cuda_bf16.h>
#include <math.h>
#include <stdint.h>

#define S_ 256
#define D_ 256
#define B_ 1024
#define LOG2PI 1.8378770664093453f

// Scratch (no runtime allocation allowed)
__device__ float g_M[S_ * D_ * D_];    // Gram -> overwritten in place by L (lower)
__device__ float g_LT[S_ * D_ * D_];   // L transposed (k-major), lower part valid
__device__ float g_W[S_ * D_ * D_];    // W = L^{-1} fp32 (used inside cholinv)
__device__ float g_logdet[S_];
// bf16 hi/lo split arrays. Phase 1: transposed sp ([s][d][k]) for gram.
// Phase 2 (after gram consumed them): W split ([s][row][col]) for maha.
__device__ __nv_bfloat16 g_bfH[S_ * D_ * D_];
__device__ __nv_bfloat16 g_bfL[S_ * D_ * D_];

// ---------------------------------------------------------------------------
// helpers
// ---------------------------------------------------------------------------
__device__ __forceinline__ uint32_t smem_u32(const void* p) {
    uint32_t a;
    asm("{ .reg .u64 t; cvta.to.shared.u64 t, %1; cvt.u32.u64 %0, t; }"
        : "=r"(a) : "l"(p));
    return a;
}
#define LDSM_X4(r, addr) \
    asm volatile("ldmatrix.sync.aligned.m8n8.x4.shared.b16 {%0,%1,%2,%3}, [%4];" \
                 : "=r"((r)[0]), "=r"((r)[1]), "=r"((r)[2]), "=r"((r)[3]) \
                 : "r"(addr))
#define LDSM_X2(r, addr) \
    asm volatile("ldmatrix.sync.aligned.m8n8.x2.shared.b16 {%0,%1}, [%2];" \
                 : "=r"((r)[0]), "=r"((r)[1]) : "r"(addr))
#define MMA16816(c, a, b) \
    asm volatile("mma.sync.aligned.m16n8k16.row.col.f32.bf16.bf16.f32 " \
                 "{%0,%1,%2,%3}, {%4,%5,%6,%7}, {%8,%9}, {%0,%1,%2,%3};" \
                 : "+f"((c)[0]), "+f"((c)[1]), "+f"((c)[2]), "+f"((c)[3]) \
                 : "r"((a)[0]), "r"((a)[1]), "r"((a)[2]), "r"((a)[3]), \
                   "r"((b)[0]), "r"((b)[1]))

__device__ __forceinline__ uint32_t pack_split(float f0, float f1, uint32_t& lo) {
    __nv_bfloat16 h0 = __float2bfloat16(f0);
    __nv_bfloat16 h1 = __float2bfloat16(f1);
    __nv_bfloat16 l0 = __float2bfloat16(f0 - __bfloat162float(h0));
    __nv_bfloat16 l1 = __float2bfloat16(f1 - __bfloat162float(h1));
    __nv_bfloat162 hp = __halves2bfloat162(h0, h1);
    __nv_bfloat162 lp = __halves2bfloat162(l0, l1);
    lo = *(uint32_t*)&lp;
    return *(uint32_t*)&hp;
}
__device__ __forceinline__ void split8(float4 a, float4 b, uint4& h, uint4& l) {
    h.x = pack_split(a.x, a.y, l.x);
    h.y = pack_split(a.z, a.w, l.y);
    h.z = pack_split(b.x, b.y, l.z);
    h.w = pack_split(b.z, b.w, l.w);
}

// ---------------------------------------------------------------------------
// Kernel 0: tsplit — sp (fp32 [s][k][d]) -> g_bfH/g_bfL (bf16, TRANSPOSED [s][d][k])
// Block = (tile16, s): 64x64 tile transpose via smem.
// ---------------------------------------------------------------------------
__global__ __launch_bounds__(256) void tsplit_kernel(const float* __restrict__ sp) {
    __shared__ unsigned short H[64][72];
    __shared__ unsigned short L[64][72];
    const int s = blockIdx.y;
    const int k0 = (blockIdx.x >> 2) * 64;
    const int d0 = (blockIdx.x & 3) * 64;
    const int t = threadIdx.x;
    const int r16 = t >> 4, c4 = (t & 15) * 4;

#pragma unroll
    for (int rr = 0; rr < 4; ++rr) {
        int kr = rr * 16 + r16;
        float4 v = *(const float4*)&sp[s * 65536 + (k0 + kr) * 256 + d0 + c4];
        uint32_t l01, l23;
        uint32_t h01 = pack_split(v.x, v.y, l01);
        uint32_t h23 = pack_split(v.z, v.w, l23);
        *(uint32_t*)&H[kr][c4]     = h01;
        *(uint32_t*)&H[kr][c4 + 2] = h23;
        *(uint32_t*)&L[kr][c4]     = l01;
        *(uint32_t*)&L[kr][c4 + 2] = l23;
    }
    __syncthreads();

    const int dr = t >> 2, q = t & 3;
#pragma unroll
    for (int h = 0; h < 2; ++h) {
        int kc = q * 16 + h * 8;
        uint32_t wh[4], wl[4];
#pragma unroll
        for (int j = 0; j < 4; ++j) {
            wh[j] = (uint32_t)H[kc + 2 * j][dr] | ((uint32_t)H[kc + 2 * j + 1][dr] << 16);
            wl[j] = (uint32_t)L[kc + 2 * j][dr] | ((uint32_t)L[kc + 2 * j + 1][dr] << 16);
        }
        int gi = s * 65536 + (d0 + dr) * 256 + k0 + kc;
        *(uint4*)&g_bfH[gi] = make_uint4(wh[0], wh[1], wh[2], wh[3]);
        *(uint4*)&g_bfL[gi] = make_uint4(wl[0], wl[1], wl[2], wl[3]);
    }
}

// ---------------------------------------------------------------------------
// Kernel 1: Gram via HMMA bf16 split. M[s] = Sp^T Sp, tiles (0,0),(1,0),(1,1).
// Operands from g_bfH/g_bfL (transposed [d][k] layout, k-contiguous).
// ---------------------------------------------------------------------------
#define ASTRIDE 72
#define ABUF (128 * ASTRIDE)
#define GEMM_SMEM (4 * ABUF * 2)

__global__ __launch_bounds__(256) void gram_mma_kernel() {
    extern __shared__ char shm[];
    __nv_bfloat16* AH = (__nv_bfloat16*)shm;
    __nv_bfloat16* AL = AH + ABUF;
    __nv_bfloat16* BH = AL + ABUF;
    __nv_bfloat16* BL = BH + ABUF;

    const int t = blockIdx.x;            // 0:(0,0) 1:(1,0) 2:(1,1)
    const int s = blockIdx.y;
    const int di = (t == 0) ? 0 : 1;
    const int ei = (t == 2) ? 1 : 0;
    const int tid = threadIdx.x;
    const int wid = tid >> 5, lane = tid & 31;
    const int wr = wid >> 2, wc = wid & 3;

    float c[4][4][4];
#pragma unroll
    for (int mt = 0; mt < 4; ++mt)
#pragma unroll
        for (int nt = 0; nt < 4; ++nt)
#pragma unroll
            for (int q = 0; q < 4; ++q) c[mt][nt][q] = 0.f;

    const int rowq = tid >> 1, half = tid & 1;
    const int sb = s * 65536;

    for (int ch = 0; ch < 4; ++ch) {
        const int k0 = ch * 64;
        __syncthreads();
#pragma unroll
        for (int j = 0; j < 4; ++j) {
            int kc = half * 32 + j * 8;
            int ga = sb + (di * 128 + rowq) * 256 + k0 + kc;
            int gb = sb + (ei * 128 + rowq) * 256 + k0 + kc;
            *(uint4*)(AH + rowq * ASTRIDE + kc) = *(const uint4*)&g_bfH[ga];
            *(uint4*)(AL + rowq * ASTRIDE + kc) = *(const uint4*)&g_bfL[ga];
            *(uint4*)(BH + rowq * ASTRIDE + kc) = *(const uint4*)&g_bfH[gb];
            *(uint4*)(BL + rowq * ASTRIDE + kc) = *(const uint4*)&g_bfL[gb];
        }
        __syncthreads();

        const int ar = lane & 15, as8 = (lane >> 4) * 8;
        const int br = lane & 7,  bs8 = ((lane >> 3) & 1) * 8;
#pragma unroll
        for (int ks = 0; ks < 4; ++ks) {
            const int kk = ks * 16;
            uint32_t aH[4][4], aL[4][4], bH[4][2], bL[4][2];
#pragma unroll
            for (int mt = 0; mt < 4; ++mt) {
                int row = wr * 64 + mt * 16 + ar;
                LDSM_X4(aH[mt], smem_u32(AH + row * ASTRIDE + kk + as8));
                LDSM_X4(aL[mt], smem_u32(AL + row * ASTRIDE + kk + as8));
            }
#pragma unroll
            for (int nt = 0; nt < 4; ++nt) {
                int row = wc * 32 + nt * 8 + br;
                LDSM_X2(bH[nt], smem_u32(BH + row * ASTRIDE + kk + bs8));
                LDSM_X2(bL[nt], smem_u32(BL + row * ASTRIDE + kk + bs8));
            }
#pragma unroll
            for (int mt = 0; mt < 4; ++mt)
#pragma unroll
                for (int nt = 0; nt < 4; ++nt) {
                    MMA16816(c[mt][nt], aH[mt], bH[nt]);
                    MMA16816(c[mt][nt], aH[mt], bL[nt]);
                    MMA16816(c[mt][nt], aL[mt], bH[nt]);
                }
        }
    }

    // store C tile (fp32) to g_M
    float* Cg = g_M + sb;
#pragma unroll
    for (int mt = 0; mt < 4; ++mt)
#pragma unroll
        for (int nt = 0; nt < 4; ++nt) {
            int r0 = di * 128 + wr * 64 + mt * 16 + (lane >> 2);
            int cc = ei * 128 + wc * 32 + nt * 8 + (lane & 3) * 2;
            *(float2*)&Cg[r0 * 256 + cc]       = make_float2(c[mt][nt][0], c[mt][nt][1]);
            *(float2*)&Cg[(r0 + 8) * 256 + cc] = make_float2(c[mt][nt][2], c[mt][nt][3]);
        }
}

// ---------------------------------------------------------------------------
// Kernel 2: blocked Cholesky + logdet + blocked inversion.
// W stores now also emit bf16 hi/lo into g_bfH/g_bfL (consumed by maha).
// ---------------------------------------------------------------------------
#define PPAD 68
#define P_FLOATS (256 * PPAD)
#define STG_FLOATS (64 * PPAD)
#define CHOL_SMEM_FLOATS (P_FLOATS + 2 * STG_FLOATS + 256)

__global__ __launch_bounds__(256) void cholinv_kernel() {
    extern __shared__ float sh[];
    float* P   = sh;
    float* As  = sh + P_FLOATS;
    float* Bs  = sh + P_FLOATS + STG_FLOATS;
    float* red = sh + P_FLOATS + 2 * STG_FLOATS;

    const int s = blockIdx.x;
    const int tid = threadIdx.x;
    const int sb = s * 65536;
    const float* Ms = g_M + sb;
    float* Mw = g_M + sb;
    float* LT = g_LT + sb;
    float* Wg = g_W + sb;

    const int rg = (tid >> 4) * 4;
    const int cg = (tid & 15) * 4;

    red[tid] = Ms[tid * D_ + tid];
    __syncthreads();
    for (int o = 128; o > 0; o >>= 1) {
        if (tid < o) red[tid] += red[tid + o];
        __syncthreads();
    }
    const float ridge = 0.01f * red[0] / (float)D_;
    __syncthreads();

    for (int J = 0; J < 4; ++J) {
        const int R = 256 - 64 * J;
        const int g0 = 64 * J;

        for (int e = tid; e < R * 16; e += 256) {
            int pr = e >> 4, c4 = (e & 15) * 4;
            float4 v = *(const float4*)&Ms[(g0 + pr) * D_ + g0 + c4];
            *(float4*)&P[pr * PPAD + c4] = v;
        }
        __syncthreads();
        if (tid < 64) P[tid * PPAD + tid] += ridge;
        __syncthreads();

        for (int K = 0; K < J; ++K) {
            __syncthreads();
            for (int e = tid; e < 1024; e += 256) {
                int k = e >> 4, c4 = (e & 15) * 4;
                float4 v = *(const float4*)&LT[(64 * K + k) * D_ + g0 + c4];
                *(float4*)&Bs[k * PPAD + c4] = v;
            }
            for (int I = J; I < 4; ++I) {
                __syncthreads();
                for (int e = tid; e < 1024; e += 256) {
                    int k = e >> 4, r4 = (e & 15) * 4;
                    float4 v = *(const float4*)&LT[(64 * K + k) * D_ + 64 * I + r4];
                    *(float4*)&As[k * PPAD + r4] = v;
                }
                __syncthreads();
                float acc[4][4];
#pragma unroll
                for (int r = 0; r < 4; ++r)
#pragma unroll
                    for (int c = 0; c < 4; ++c) acc[r][c] = 0.f;
#pragma unroll 4
                for (int kk = 0; kk < 64; ++kk) {
                    float4 a = *(const float4*)&As[kk * PPAD + rg];
                    float4 b = *(const float4*)&Bs[kk * PPAD + cg];
                    float av[4] = {a.x, a.y, a.z, a.w};
                    float bv[4] = {b.x, b.y, b.z, b.w};
#pragma unroll
                    for (int r = 0; r < 4; ++r)
#pragma unroll
                        for (int c = 0; c < 4; ++c) acc[r][c] += av[r] * bv[c];
                }
                const int prb = 64 * (I - J);
#pragma unroll
                for (int r = 0; r < 4; ++r)
#pragma unroll
                    for (int c = 0; c < 4; ++c)
                        P[(prb + rg + r) * PPAD + cg + c] -= acc[r][c];
            }
        }
        __syncthreads();

        for (int jj = 0; jj < 64; ++jj) {
            const int pr = jj + tid;
            const bool act = pr < R;
            float num = 0.f;
            if (act) {
                const float* rp = P + pr * PPAD;
                const float* rj = P + jj * PPAD;
                float a0 = 0.f, a1 = 0.f, a2 = 0.f, a3 = 0.f;
                const int j4 = jj & ~3;
                for (int k = 0; k < j4; k += 4) {
                    float4 u = *(const float4*)(rp + k);
                    float4 v = *(const float4*)(rj + k);
                    a0 += u.x * v.x; a1 += u.y * v.y;
                    a2 += u.z * v.z; a3 += u.w * v.w;
                }
                for (int k = j4; k < jj; ++k) a0 += rp[k] * rj[k];
                num = rp[jj] - ((a0 + a1) + (a2 + a3));
            }
            if (tid == 0) red[0] = num;
            __syncthreads();
            const float dj = sqrtf(red[0]);
            if (act) P[pr * PPAD + jj] = (tid == 0) ? dj : num / dj;
            __syncthreads();
        }

        for (int e = tid; e < R * 16; e += 256) {
            int pr = e >> 4, c4 = (e & 15) * 4;
            float4 v = *(const float4*)&P[pr * PPAD + c4];
            *(float4*)&Mw[(g0 + pr) * D_ + g0 + c4] = v;
        }
        for (int c = 0; c < 64; ++c) {
            for (int pr = tid; pr < R; pr += 256)
                LT[(g0 + c) * D_ + g0 + pr] = P[pr * PPAD + c];
        }
        __syncthreads();
    }

    red[tid] = 2.f * logf(Mw[tid * D_ + tid]);
    __syncthreads();
    for (int o = 128; o > 0; o >>= 1) {
        if (tid < o) red[tid] += red[tid + o];
        __syncthreads();
    }
    if (tid == 0) g_logdet[s] = red[0];
    __syncthreads();

    // ===== blocked inversion: W = L^{-1} =====
    for (int t = tid; t < 16384; t += 256) P[t] = 0.f;
    __syncthreads();

    for (int rnd = 0; rnd < 2; ++rnd) {
        for (int e = tid; e < 1024; e += 256) {
            int ii = e >> 4, t4 = (e & 15) * 4;
            int K0 = 2 * rnd, K1 = 2 * rnd + 1;
            *(float4*)&As[ii * 64 + t4] =
                *(const float4*)&Mw[(64 * K0 + ii) * D_ + 64 * K0 + t4];
            *(float4*)&Bs[ii * 64 + t4] =
                *(const float4*)&Mw[(64 * K1 + ii) * D_ + 64 * K1 + t4];
        }
        __syncthreads();
        if (tid < 128) {
            const int g = tid >> 6;
            const int jj = tid & 63;
            const int K = 2 * rnd + g;
            float* WK = P + K * 4096;
            const float* Ld = g ? Bs : As;
            for (int ii = jj; ii < 64; ++ii) {
                float acc = (ii == jj) ? 1.f : 0.f;
                for (int t = jj; t < ii; ++t) acc -= Ld[ii * 64 + t] * WK[t * 64 + jj];
                WK[ii * 64 + jj] = acc / Ld[ii * 64 + ii];
            }
        }
        __syncthreads();
    }

    // diag-inverse blocks -> Wg (fp32) + g_bfH/g_bfL (bf16 split), incl. zero uppers
    for (int e = tid; e < 8192; e += 256) {
        int Kb = e >> 11, rr = (e >> 5) & 63, c2 = (e & 31) * 2;
        float v0 = P[Kb * 4096 + rr * 64 + c2];
        float v1 = P[Kb * 4096 + rr * 64 + c2 + 1];
        int gi = (64 * Kb + rr) * D_ + 64 * Kb + c2;
        Wg[gi] = v0; Wg[gi + 1] = v1;
        uint32_t lo, hi = pack_split(v0, v1, lo);
        *(uint32_t*)&g_bfH[sb + gi] = hi;
        *(uint32_t*)&g_bfL[sb + gi] = lo;
    }
    // zero the 6 strictly-upper 64x64 blocks (maha/gram sweep them)
    for (int e = tid; e < 6 * 2048; e += 256) {
        int bb = e >> 11, rr = (e >> 5) & 63, c2 = (e & 31) * 2;
        int I = (bb < 3) ? 0 : ((bb < 5) ? 1 : 2);
        int J = (bb < 3) ? (bb + 1) : ((bb == 3) ? 2 : 3);
        int gi = (64 * I + rr) * D_ + 64 * J + c2;
        Wg[gi] = 0.f; Wg[gi + 1] = 0.f;
        *(uint32_t*)&g_bfH[sb + gi] = 0u;
        *(uint32_t*)&g_bfL[sb + gi] = 0u;
    }
    __syncthreads();

    // Phase B: W(I,J) = -Wd[I] * (sum_{K=J..I-1} L(I,K) * W(K,J))
    for (int J = 0; J < 3; ++J) {
        for (int I = J + 1; I < 4; ++I) {
            float acc[4][4];
#pragma unroll
            for (int r = 0; r < 4; ++r)
#pragma unroll
                for (int c = 0; c < 4; ++c) acc[r][c] = 0.f;

            for (int K = J; K < I; ++K) {
                __syncthreads();
                for (int e = tid; e < 1024; e += 256) {
                    int k = e >> 4, r4 = (e & 15) * 4;
                    float4 v = *(const float4*)&LT[(64 * K + k) * D_ + 64 * I + r4];
                    *(float4*)&As[k * PPAD + r4] = v;
                }
                for (int e = tid; e < 1024; e += 256) {
                    int k = e >> 4, c4 = (e & 15) * 4;
                    float4 v;
                    if (K == J) {
                        v = make_float4(P[J * 4096 + k * 64 + c4 + 0],
                                        P[J * 4096 + k * 64 + c4 + 1],
                                        P[J * 4096 + k * 64 + c4 + 2],
                                        P[J * 4096 + k * 64 + c4 + 3]);
                    } else {
                        v = *(const float4*)&Wg[(64 * K + k) * D_ + 64 * J + c4];
                    }
                    *(float4*)&Bs[k * PPAD + c4] = v;
                }
                __syncthreads();
#pragma unroll 4
                for (int kk = 0; kk < 64; ++kk) {
                    float4 a = *(const float4*)&As[kk * PPAD + rg];
                    float4 b = *(const float4*)&Bs[kk * PPAD + cg];
                    float av[4] = {a.x, a.y, a.z, a.w};
                    float bv[4] = {b.x, b.y, b.z, b.w};
#pragma unroll
                    for (int r = 0; r < 4; ++r)
#pragma unroll
                        for (int c = 0; c < 4; ++c) acc[r][c] += av[r] * bv[c];
                }
            }
            __syncthreads();
#pragma unroll
            for (int r = 0; r < 4; ++r)
#pragma unroll
                for (int c = 0; c < 4; ++c)
                    Bs[(rg + r) * PPAD + cg + c] = acc[r][c];
            __syncthreads();
            float o[4][4];
#pragma unroll
            for (int r = 0; r < 4; ++r)
#pragma unroll
                for (int c = 0; c < 4; ++c) o[r][c] = 0.f;
            const float* wA = P + I * 4096;
#pragma unroll 4
            for (int kk = 0; kk < 64; ++kk) {
                float av[4];
#pragma unroll
                for (int r = 0; r < 4; ++r) av[r] = wA[(rg + r) * 64 + kk];
                float4 b = *(const float4*)&Bs[kk * PPAD + cg];
                float bv[4] = {b.x, b.y, b.z, b.w};
#pragma unroll
                for (int r = 0; r < 4; ++r)
#pragma unroll
                    for (int c = 0; c < 4; ++c) o[r][c] += av[r] * bv[c];
            }
#pragma unroll
            for (int r = 0; r < 4; ++r) {
                float n0 = -o[r][0], n1 = -o[r][1], n2 = -o[r][2], n3 = -o[r][3];
                int gi = (64 * I + rg + r) * D_ + 64 * J + cg;
                *(float4*)&Wg[gi] = make_float4(n0, n1, n2, n3);
                uint32_t l01, l23;
                uint32_t h01 = pack_split(n0, n1, l01);
                uint32_t h23 = pack_split(n2, n3, l23);
                *(uint2*)&g_bfH[sb + gi] = make_uint2(h01, h23);
                *(uint2*)&g_bfL[sb + gi] = make_uint2(l01, l23);
            }
        }
    }
}

// ---------------------------------------------------------------------------
// Kernel 3: maha via mma.sync bf16 split GEMM + square-reduce epilogue.
// A operand now loaded pre-split from g_bfH/g_bfL (no fp32 load/convert).
// ---------------------------------------------------------------------------
#define MAHA_SMEM (4 * ABUF * 2 + 256 * 4)

__global__ __launch_bounds__(256) void maha_mma_kernel(const float* __restrict__ x,
                                                       const float* __restrict__ mu,
                                                       float* __restrict__ out) {
    extern __shared__ char shm[];
    __nv_bfloat16* AH = (__nv_bfloat16*)shm;
    __nv_bfloat16* AL = AH + ABUF;
    __nv_bfloat16* BH = AL + ABUF;
    __nv_bfloat16* BL = BH + ABUF;
    float* sacc = (float*)(shm + 4 * ABUF * 2);   // [2 warp-rows][128 cols]

    const int s = blockIdx.y;
    const int b0 = blockIdx.x * 128;
    const int tid = threadIdx.x;
    const int wid = tid >> 5, lane = tid & 31;
    const int wr = wid >> 2;
    const int wc = wid & 3;

    sacc[tid] = 0.f;
    __syncthreads();

    const int sb = s * 65536;
    const int srow = tid >> 3;              // 0..31 (B staging row group)
    const int sk8  = (tid & 7) * 8;
    const int rowq = tid >> 1, half = tid & 1;   // A staging

    for (int dt = 0; dt < 2; ++dt) {
        float c[4][4][4];
#pragma unroll
        for (int mt = 0; mt < 4; ++mt)
#pragma unroll
            for (int nt = 0; nt < 4; ++nt)
#pragma unroll
                for (int q = 0; q < 4; ++q) c[mt][nt][q] = 0.f;

        const int nch = dt ? 4 : 2;          // d-tile 0: W zero beyond k=128
        for (int ch = 0; ch < nch; ++ch) {
            const int k0 = ch * 64;
            __syncthreads();
            // ---- stage A: direct bf16 copies from g_bfH/g_bfL ----
#pragma unroll
            for (int j = 0; j < 4; ++j) {
                int kc = half * 32 + j * 8;
                int ga = sb + (dt * 128 + rowq) * 256 + k0 + kc;
                *(uint4*)(AH + rowq * ASTRIDE + kc) = *(const uint4*)&g_bfH[ga];
                *(uint4*)(AL + rowq * ASTRIDE + kc) = *(const uint4*)&g_bfL[ga];
            }
            // ---- stage B = x[b0+row] - mu[s], split on the fly ----
#pragma unroll
            for (int it = 0; it < 4; ++it) {
                int row = srow + it * 32;
                const float* px = x + (b0 + row) * 256 + k0 + sk8;
                const float* pm = mu + s * 256 + k0 + sk8;
                float4 u = *(const float4*)px;
                float4 um = *(const float4*)pm;
                float4 v = *(const float4*)(px + 4);
                float4 vm = *(const float4*)(pm + 4);
                u.x -= um.x; u.y -= um.y; u.z -= um.z; u.w -= um.w;
                v.x -= vm.x; v.y -= vm.y; v.z -= vm.z; v.w -= vm.w;
                uint4 hq, lq; split8(u, v, hq, lq);
                *(uint4*)(BH + row * ASTRIDE + sk8) = hq;
                *(uint4*)(BL + row * ASTRIDE + sk8) = lq;
            }
            __syncthreads();

            const int ar = lane & 15, as8 = (lane >> 4) * 8;
            const int br = lane & 7,  bs8 = ((lane >> 3) & 1) * 8;
#pragma unroll
            for (int ks = 0; ks < 4; ++ks) {
                const int kk = ks * 16;
                uint32_t aH[4][4], aL[4][4], bH[4][2], bL[4][2];
#pragma unroll
                for (int mt = 0; mt < 4; ++mt) {
                    int row = wr * 64 + mt * 16 + ar;
                    LDSM_X4(aH[mt], smem_u32(AH + row * ASTRIDE + kk + as8));
                    LDSM_X4(aL[mt], smem_u32(AL + row * ASTRIDE + kk + as8));
                }
#pragma unroll
                for (int nt = 0; nt < 4; ++nt) {
                    int row = wc * 32 + nt * 8 + br;
                    LDSM_X2(bH[nt], smem_u32(BH + row * ASTRIDE + kk + bs8));
                    LDSM_X2(bL[nt], smem_u32(BL + row * ASTRIDE + kk + bs8));
                }
#pragma unroll
                for (int mt = 0; mt < 4; ++mt)
#pragma unroll
                    for (int nt = 0; nt < 4; ++nt) {
                        MMA16816(c[mt][nt], aH[mt], bH[nt]);
                        MMA16816(c[mt][nt], aH[mt], bL[nt]);
                        MMA16816(c[mt][nt], aL[mt], bH[nt]);
                    }
            }
        }

        // ---- epilogue: square + reduce over d within warp, slot-accumulate ----
#pragma unroll
        for (int nt = 0; nt < 4; ++nt) {
            float p0 = 0.f, p1 = 0.f;
#pragma unroll
            for (int mt = 0; mt < 4; ++mt) {
                p0 += c[mt][nt][0] * c[mt][nt][0] + c[mt][nt][2] * c[mt][nt][2];
                p1 += c[mt][nt][1] * c[mt][nt][1] + c[mt][nt][3] * c[mt][nt][3];
            }
#pragma unroll
            for (int m = 4; m <= 16; m <<= 1) {
                p0 += __shfl_xor_sync(0xffffffffu, p0, m);
                p1 += __shfl_xor_sync(0xffffffffu, p1, m);
            }
            if (lane < 4) {
                int col = wc * 32 + nt * 8 + 2 * lane;
                sacc[wr * 128 + col]     += p0;
                sacc[wr * 128 + col + 1] += p1;
            }
        }
    }

    __syncthreads();
    if (tid < 128) {
        float m = sacc[tid] + sacc[128 + tid];
        out[(b0 + tid) * S_ + s] = -0.5f * ((float)D_ * LOG2PI + g_logdet[s] + m);
    }
}

// ---------------------------------------------------------------------------
extern "C" void kernel_launch(void* const* d_in, const int* in_sizes, int n_in,
                              void* d_out, int out_size) {
    const float* x  = (const float*)d_in[0];   // (B, D)
    const float* mu = (const float*)d_in[1];   // (S, 1, D)
    const float* sp = (const float*)d_in[2];   // (S, 1, D, D)
    float* out = (float*)d_out;                // (B, S)

    const int chol_smem = CHOL_SMEM_FLOATS * sizeof(float);   // 105,472 B
    cudaFuncSetAttribute(cholinv_kernel,
                         cudaFuncAttributeMaxDynamicSharedMemorySize, chol_smem);
    cudaFuncSetAttribute(gram_mma_kernel,
                         cudaFuncAttributeMaxDynamicSharedMemorySize, GEMM_SMEM);
    cudaFuncSetAttribute(maha_mma_kernel,
                         cudaFuncAttributeMaxDynamicSharedMemorySize, MAHA_SMEM);

    tsplit_kernel<<<dim3(16, S_), 256>>>(sp);
    gram_mma_kernel<<<dim3(3, S_), 256, GEMM_SMEM>>>();
    cholinv_kernel<<<S_, 256, chol_smem>>>();
    maha_mma_kernel<<<dim3(B_ / 128, S_), 256, MAHA_SMEM>>>(x, mu, out);
}